// round 16
// baseline (speedup 1.0000x reference)
#include <cuda_runtime.h>
#include <cuda_bf16.h>
#include <math.h>
#include <stdint.h>

#define Bsz 256
#define Tt  128
#define Nn  512
#define Hh  128
#define G4  512   // 4*H

// Device scratch (no runtime alloc)
__device__ float g_Gpre[(size_t)Bsz * Tt * G4];          // 64 MB gate preacts
__device__ float g_whhT[Hh * G4];
__device__ __nv_bfloat16 g_Ahi[(size_t)Bsz * Tt * Nn];   // 32 MB
__device__ __nv_bfloat16 g_Alo[(size_t)Bsz * Tt * Nn];   // 32 MB
__device__ __nv_bfloat16 g_Whi[G4 * Nn];
__device__ __nv_bfloat16 g_Wlo[G4 * Nn];

// ======================= PTX helpers (generic-target only) ==================
__device__ __forceinline__ uint32_t smem_u32(const void* p) {
    uint32_t a;
    asm("{ .reg .u64 t; cvta.to.shared.u64 t, %1; cvt.u32.u64 %0, t; }"
        : "=r"(a) : "l"(p));
    return a;
}
__device__ __forceinline__ void cpa16(uint32_t dst, const void* src) {
    asm volatile("cp.async.cg.shared.global [%0], [%1], 16;"
                 :: "r"(dst), "l"(src) : "memory");
}
__device__ __forceinline__ void cpa_commit() {
    asm volatile("cp.async.commit_group;" ::: "memory");
}
__device__ __forceinline__ void cpa_wait0() {
    asm volatile("cp.async.wait_group 0;" ::: "memory");
}
__device__ __forceinline__ void cpa_wait1() {
    asm volatile("cp.async.wait_group 1;" ::: "memory");
}
__device__ __forceinline__ void ldsm4(uint32_t* r, uint32_t a) {
    asm volatile("ldmatrix.sync.aligned.m8n8.x4.shared.b16 {%0,%1,%2,%3}, [%4];"
                 : "=r"(r[0]), "=r"(r[1]), "=r"(r[2]), "=r"(r[3]) : "r"(a));
}
__device__ __forceinline__ void mma16816(float* d, const uint32_t* a,
                                         const uint32_t* b) {
    asm volatile("mma.sync.aligned.m16n8k16.row.col.f32.bf16.bf16.f32 "
        "{%0,%1,%2,%3}, {%4,%5,%6,%7}, {%8,%9}, {%0,%1,%2,%3};"
        : "+f"(d[0]), "+f"(d[1]), "+f"(d[2]), "+f"(d[3])
        : "r"(a[0]), "r"(a[1]), "r"(a[2]), "r"(a[3]), "r"(b[0]), "r"(b[1]));
}
// Packed fp32x2 FMA (exact fp32 pair; may scalarize on this toolchain)
__device__ __forceinline__ void fma2(unsigned long long& d,
                                     unsigned long long a, unsigned long long b) {
    asm("fma.rn.f32x2 %0, %1, %2, %0;" : "+l"(d) : "l"(a), "l"(b));
}
__device__ __forceinline__ unsigned long long dup2(float v) {
    unsigned long long r;
    asm("mov.b64 %0, {%1, %1};" : "=l"(r) : "f"(v));
    return r;
}
__device__ __forceinline__ float ull_lo(unsigned long long v) {
    return __uint_as_float((uint32_t)(v & 0xffffffffull));
}
__device__ __forceinline__ float ull_hi(unsigned long long v) {
    return __uint_as_float((uint32_t)(v >> 32));
}
__device__ __forceinline__ void barx(int id, int cnt) {
    asm volatile("bar.sync %0, %1;" :: "r"(id), "r"(cnt) : "memory");
}
// Swizzled smem address for GEMM tiles: rows of 64B (4 x 16B granules).
__device__ __forceinline__ uint32_t sw_addr(uint32_t base, int r, int c) {
    uint32_t g = (uint32_t)(r * 4 + c);
    return base + ((g ^ ((g >> 2) & 7)) << 4);
}

// ---------------------------------------------------------------------------
// w_hh (4H, H) -> w_hhT (H, 4H)
// ---------------------------------------------------------------------------
__global__ void k_transpose_whh(const float* __restrict__ whh) {
    int idx = blockIdx.x * blockDim.x + threadIdx.x;
    if (idx < Hh * G4) {
        int k = idx >> 9;
        int j = idx & 511;
        g_whhT[idx] = whh[j * Hh + k];
    }
}

// ---------------------------------------------------------------------------
// w_ih -> hi/lo bf16 split
// ---------------------------------------------------------------------------
__global__ void k_convert_w(const float* __restrict__ wih) {
    int idx = blockIdx.x * blockDim.x + threadIdx.x;
    if (idx < G4 * Nn) {
        float v = wih[idx];
        __nv_bfloat16 hi = __float2bfloat16(v);
        g_Whi[idx] = hi;
        g_Wlo[idx] = __float2bfloat16(v - __bfloat162float(hi));
    }
}

// ---------------------------------------------------------------------------
// alpha = softmax_n(sum_t X*w_x); Xt = alpha .* X (time-invariant alpha).
// Also emits the hi/lo bf16 split of Xt for the tensor-core GEMM.
// ---------------------------------------------------------------------------
__global__ __launch_bounds__(512) void k_alpha(const float* __restrict__ X,
                                               const float* __restrict__ attn_w,
                                               float* __restrict__ Xt) {
    int b = blockIdx.x;
    int n = threadIdx.x;
    __shared__ float wx[Tt];
    __shared__ float redm[17];
    __shared__ float reds[17];
    if (n < Tt) wx[n] = attn_w[2 * Hh + n];
    __syncthreads();

    const float* Xb = X + (size_t)b * Tt * Nn;
    float acc = 0.f;
#pragma unroll 8
    for (int t = 0; t < Tt; t++)
        acc = fmaf(Xb[t * Nn + n], wx[t], acc);

    float v = acc;
#pragma unroll
    for (int o = 16; o > 0; o >>= 1)
        v = fmaxf(v, __shfl_xor_sync(0xffffffffu, v, o));
    if ((n & 31) == 0) redm[n >> 5] = v;
    __syncthreads();
    if (n < 32) {
        float m = (n < 16) ? redm[n] : -3.402823466e38f;
#pragma unroll
        for (int o = 16; o > 0; o >>= 1)
            m = fmaxf(m, __shfl_xor_sync(0xffffffffu, m, o));
        if (n == 0) redm[16] = m;
    }
    __syncthreads();
    float mx = redm[16];

    float e = __expf(acc - mx);
    v = e;
#pragma unroll
    for (int o = 16; o > 0; o >>= 1)
        v += __shfl_xor_sync(0xffffffffu, v, o);
    if ((n & 31) == 0) reds[n >> 5] = v;
    __syncthreads();
    if (n < 32) {
        float s = (n < 16) ? reds[n] : 0.f;
#pragma unroll
        for (int o = 16; o > 0; o >>= 1)
            s += __shfl_xor_sync(0xffffffffu, s, o);
        if (n == 0) reds[16] = s;
    }
    __syncthreads();
    float alpha = e / reds[16];

    float* Ot = Xt + (size_t)b * Tt * Nn;
    __nv_bfloat16* Ah = g_Ahi + (size_t)b * Tt * Nn;
    __nv_bfloat16* Al = g_Alo + (size_t)b * Tt * Nn;
#pragma unroll 4
    for (int t = 0; t < Tt; t++) {
        float xv = alpha * Xb[t * Nn + n];
        Ot[t * Nn + n] = xv;
        __nv_bfloat16 hi = __float2bfloat16(xv);
        Ah[t * Nn + n] = hi;
        Al[t * Nn + n] = __float2bfloat16(xv - __bfloat162float(hi));
    }
}

// ---------------------------------------------------------------------------
// bf16x3 warp-MMA GEMM — R13 core, upgraded to a 3-stage cp.async pipeline.
// ---------------------------------------------------------------------------
#define CHUNK_BYTES 32768        // 4 tiles x 8 KB (Ahi, Alo, Bhi, Blo)
#define GT_SMEM (3 * CHUNK_BYTES)

__device__ __forceinline__ void stage_chunk(uint32_t bbase, int kc, int tid,
                                            const __nv_bfloat16* PAh,
                                            const __nv_bfloat16* PAl,
                                            const __nv_bfloat16* PBh,
                                            const __nv_bfloat16* PBl) {
    const __nv_bfloat16* P[4] = { PAh, PAl, PBh, PBl };
#pragma unroll
    for (int t = 0; t < 4; t++) {
        uint32_t toff = bbase + t * 8192;
#pragma unroll
        for (int q = 0; q < 2; q++) {
            uint32_t G = (uint32_t)tid + q * 256;   // granule 0..511
            uint32_t r = G >> 2, c = G & 3;
            uint32_t swg = G ^ ((G >> 2) & 7);
            cpa16(toff + (swg << 4), P[t] + (size_t)r * 512 + kc * 32 + c * 8);
        }
    }
}

__global__ __launch_bounds__(256) void k_gemm_mma(const float* __restrict__ bih,
                                                  const float* __restrict__ bhh) {
    extern __shared__ char smp[];
    uint32_t sb = smem_u32(smp);
    int tid  = threadIdx.x;
    int lane = tid & 31;
    int wid  = tid >> 5;
    int bn   = blockIdx.x;   // 0..3
    int bm   = blockIdx.y;   // 0..255
    int m0w  = (wid & 1) * 64;
    int n0w  = (wid >> 1) * 32;

    const __nv_bfloat16* PAh = g_Ahi + (size_t)bm * 128 * 512;
    const __nv_bfloat16* PAl = g_Alo + (size_t)bm * 128 * 512;
    const __nv_bfloat16* PBh = g_Whi + (size_t)bn * 128 * 512;
    const __nv_bfloat16* PBl = g_Wlo + (size_t)bn * 128 * 512;

    float d[4][4][4];
#pragma unroll
    for (int i = 0; i < 4; i++)
#pragma unroll
        for (int j = 0; j < 4; j++)
#pragma unroll
            for (int q = 0; q < 4; q++) d[i][j][q] = 0.f;

    stage_chunk(sb, 0, tid, PAh, PAl, PBh, PBl);
    cpa_commit();
    stage_chunk(sb + CHUNK_BYTES, 1, tid, PAh, PAl, PBh, PBl);
    cpa_commit();

    for (int kc = 0; kc < 16; kc++) {
        if (kc == 15) cpa_wait0(); else cpa_wait1();
        __syncthreads();
        if (kc + 2 < 16) {
            stage_chunk(sb + ((kc + 2) % 3) * CHUNK_BYTES, kc + 2, tid,
                        PAh, PAl, PBh, PBl);
            cpa_commit();
        }
        uint32_t Ah = sb + (kc % 3) * CHUNK_BYTES;
        uint32_t Al = Ah + 8192;
        uint32_t Bh = Ah + 16384;
        uint32_t Bl = Ah + 24576;

#pragma unroll
        for (int s = 0; s < 2; s++) {        // two K=16 steps per chunk
            uint32_t bh[4][2], bl[4][2];
#pragma unroll
            for (int jp = 0; jp < 2; jp++) { // each x4 covers 2 n-frags
                uint32_t tmp[4];
                int rowb = n0w + jp * 16 + (lane & 7) + ((lane >> 4) << 3);
                int cb   = s * 2 + ((lane >> 3) & 1);
                ldsm4(tmp, sw_addr(Bh, rowb, cb));
                bh[jp * 2][0] = tmp[0]; bh[jp * 2][1] = tmp[1];
                bh[jp * 2 + 1][0] = tmp[2]; bh[jp * 2 + 1][1] = tmp[3];
                ldsm4(tmp, sw_addr(Bl, rowb, cb));
                bl[jp * 2][0] = tmp[0]; bl[jp * 2][1] = tmp[1];
                bl[jp * 2 + 1][0] = tmp[2]; bl[jp * 2 + 1][1] = tmp[3];
            }
#pragma unroll
            for (int i = 0; i < 4; i++) {
                uint32_t ah[4], al[4];
                int rowa = m0w + i * 16 + (lane & 15);
                int ca   = s * 2 + (lane >> 4);
                ldsm4(ah, sw_addr(Ah, rowa, ca));
                ldsm4(al, sw_addr(Al, rowa, ca));
#pragma unroll
                for (int j = 0; j < 4; j++) {
                    mma16816(d[i][j], ah, bh[j]);
                    mma16816(d[i][j], ah, bl[j]);
                    mma16816(d[i][j], al, bh[j]);
                }
            }
        }
    }

    // Epilogue: bias add + fp32 store.
#pragma unroll
    for (int j = 0; j < 4; j++) {
        int col = bn * 128 + n0w + j * 8 + (lane & 3) * 2;
        float b0 = bih[col] + bhh[col];
        float b1 = bih[col + 1] + bhh[col + 1];
#pragma unroll
        for (int i = 0; i < 4; i++) {
            int row = bm * 128 + m0w + i * 16 + (lane >> 2);
            float2 v0 = make_float2(d[i][j][0] + b0, d[i][j][1] + b1);
            float2 v1 = make_float2(d[i][j][2] + b0, d[i][j][3] + b1);
            *(float2*)(g_Gpre + (size_t)row * 512 + col) = v0;
            *(float2*)(g_Gpre + (size_t)(row + 8) * 512 + col) = v1;
        }
    }
}

// ---------------------------------------------------------------------------
// LSTM recurrence v4: two INDEPENDENT 256-thread batch pipelines per block
// (named barriers 1/2), shuffle split-K reduce, reg+smem weights.
//   half = tid>>8 -> batch b0+half. Within a half:
//   lane bit0 = kk (K half: [kk*64, kk*64+64)), jgl = w8*16 + (lane>>1),
//   gates j4 = jgl*4, one batch per thread.
//   k rows [kb, kb+16): weights in registers; [kb+16, kb+64): smem (192 KB).
//   After accumulation: one shfl_xor(1) round reduces across kk; even lanes
//   store the gate quad (STS.128). Update: 128 threads/half, gs read is 4 LDS.
//   h stored as packed {h,h} with bank-skew; exp-based tanh.
// ---------------------------------------------------------------------------
#define WSROWS 48
#define WS_FLOATS (2 * WSROWS * G4)    // 49152 floats = 192 KB

__device__ __forceinline__ float sigm(float x) {
    return __fdividef(1.f, 1.f + __expf(-x));
}
__device__ __forceinline__ float tanh_e(float x) {
    return 1.f - __fdividef(2.f, __expf(2.f * x) + 1.f);
}

__global__ __launch_bounds__(512, 1) void k_recur(float* __restrict__ Xe) {
    extern __shared__ float sm[];
    float* ws = sm;                                   // [2][48][512]
    float* gs = ws + WS_FLOATS;                       // [2][512] reduced gates
    float* cs = gs + 2 * G4;                          // [2][128]
    unsigned long long* hs2 =
        (unsigned long long*)(cs + 2 * Hh);           // [2][130] {h,h} skewed

    int tid  = threadIdx.x;
    int b0   = blockIdx.x * 2;
    int half = tid >> 8;          // 0..1 -> batch
    int ht   = tid & 255;
    int lane = tid & 31;
    int w8   = (tid >> 5) & 7;
    int kk   = lane & 1;
    int jgl  = w8 * 16 + (lane >> 1);   // 0..127
    int j4   = jgl * 4;
    int kb   = kk * 64;

    // stage smem weight rows: ws[(kks*48 + r)][512] <- g_whhT row kks*64+16+r
    for (int i = tid; i < WS_FLOATS / 4; i += 512) {
        int rall = i >> 7;               // 0..95
        int col  = i & 127;
        int kks  = rall / WSROWS;
        int row  = rall % WSROWS;
        ((float4*)ws)[i] =
            *(const float4*)(g_whhT + (size_t)(kks * 64 + 16 + row) * 512 + col * 4);
    }
    if (tid < 256) cs[tid] = 0.f;
    if (tid < 260) hs2[tid] = 0ull;

    // register weight rows: k in [kb, kb+16)
    ulonglong2 wreg[8];
#pragma unroll
    for (int kr = 0; kr < 8; kr++)
        wreg[kr] = *(const ulonglong2*)(g_whhT + (size_t)(kb + kr) * 512 + j4);
    ulonglong2 wreg2[8];
#pragma unroll
    for (int kr = 0; kr < 8; kr++)
        wreg2[kr] = *(const ulonglong2*)(g_whhT + (size_t)(kb + 8 + kr) * 512 + j4);
    __syncthreads();

    const float* Gu = g_Gpre + (size_t)(b0 + half) * Tt * G4 + ht;  // ht<128 use
    const unsigned long long* hb = hs2 + half * 130 + kk * 66;      // skewed base
    const float* wsm = ws + (size_t)(kk * WSROWS) * G4 + j4;
    float* gsh = gs + half * G4;
    int barid = 1 + half;

    for (int t = 0; t < Tt; t++) {
        // prefetch gate preactivations (resolve under the matvec)
        float pi = 0.f, pf = 0.f, pgt = 0.f, po = 0.f;
        if (ht < 128) {
            const float* gp = Gu + (size_t)t * G4;
            pi  = __ldg(gp);
            pf  = __ldg(gp + Hh);
            pgt = __ldg(gp + 2 * Hh);
            po  = __ldg(gp + 3 * Hh);
        }

        unsigned long long a01 = 0ull, a23 = 0ull;
        // ---- register-weight rows [kb, kb+16) ----
#pragma unroll
        for (int kr = 0; kr < 8; kr += 2) {
            ulonglong2 hh = *(const ulonglong2*)(hb + kr);
            fma2(a01, wreg[kr].x, hh.x);     fma2(a23, wreg[kr].y, hh.x);
            fma2(a01, wreg[kr + 1].x, hh.y); fma2(a23, wreg[kr + 1].y, hh.y);
        }
#pragma unroll
        for (int kr = 0; kr < 8; kr += 2) {
            ulonglong2 hh = *(const ulonglong2*)(hb + 8 + kr);
            fma2(a01, wreg2[kr].x, hh.x);     fma2(a23, wreg2[kr].y, hh.x);
            fma2(a01, wreg2[kr + 1].x, hh.y); fma2(a23, wreg2[kr + 1].y, hh.y);
        }
        // ---- smem-weight rows [kb+16, kb+64) ----
#pragma unroll
        for (int kr = 0; kr < WSROWS; kr += 2) {
            ulonglong2 hh = *(const ulonglong2*)(hb + 16 + kr);
            ulonglong2 w0 = *(const ulonglong2*)(wsm + (size_t)(kr + 0) * G4);
            ulonglong2 w1 = *(const ulonglong2*)(wsm + (size_t)(kr + 1) * G4);
            fma2(a01, w0.x, hh.x); fma2(a23, w0.y, hh.x);
            fma2(a01, w1.x, hh.y); fma2(a23, w1.y, hh.y);
        }

        // ---- shuffle reduce across kk (lane bit 0) ----
        float x0 = ull_lo(a01), x1 = ull_hi(a01);
        float x2 = ull_lo(a23), x3 = ull_hi(a23);
        x0 += __shfl_xor_sync(0xffffffffu, x0, 1);
        x1 += __shfl_xor_sync(0xffffffffu, x1, 1);
        x2 += __shfl_xor_sync(0xffffffffu, x2, 1);
        x3 += __shfl_xor_sync(0xffffffffu, x3, 1);
        if (kk == 0)
            *(float4*)(gsh + j4) = make_float4(x0, x1, x2, x3);
        barx(barid, 256);

        // ---- cell update (128 threads per half) ----
        if (ht < 128) {
            float gi = pi  + gsh[ht];
            float gf = pf  + gsh[Hh + ht];
            float gg = pgt + gsh[2 * Hh + ht];
            float go = po  + gsh[3 * Hh + ht];
            float cn = sigm(gf) * cs[half * Hh + ht] + sigm(gi) * tanh_e(gg);
            float hn = sigm(go) * tanh_e(cn);
            cs[half * Hh + ht] = cn;
            hs2[half * 130 + ht + ((ht >> 6) << 1)] = dup2(hn);
            Xe[((size_t)(b0 + half) * Tt + t) * Hh + ht] = hn;
        }
        barx(barid, 256);
    }
}

// ---------------------------------------------------------------------------
extern "C" void kernel_launch(void* const* d_in, const int* in_sizes, int n_in,
                              void* d_out, int out_size) {
    const float* X      = (const float*)d_in[0];
    const float* attn_w = (const float*)d_in[1];
    // d_in[2] = attn_b: dead (softmax shift-invariance), as are attn_w[0:2H]
    const float* w_ih   = (const float*)d_in[3];
    const float* w_hh   = (const float*)d_in[4];
    const float* b_ih   = (const float*)d_in[5];
    const float* b_hh   = (const float*)d_in[6];

    float* out = (float*)d_out;
    float* Xt  = out;                                  // (B,T,N)
    float* Xe  = out + (size_t)Bsz * Tt * Nn;          // (B,T,H)

    const int recur_smem =
        (WS_FLOATS + 2 * G4 + 2 * Hh) * (int)sizeof(float) + 2 * 130 * 8;
    cudaFuncSetAttribute(k_recur, cudaFuncAttributeMaxDynamicSharedMemorySize,
                         recur_smem);
    cudaFuncSetAttribute(k_gemm_mma, cudaFuncAttributeMaxDynamicSharedMemorySize,
                         GT_SMEM);

    k_transpose_whh<<<(Hh * G4 + 255) / 256, 256>>>(w_hh);
    k_convert_w<<<(G4 * Nn + 255) / 256, 256>>>(w_ih);
    k_alpha<<<Bsz, 512>>>(X, attn_w, Xt);
    k_gemm_mma<<<dim3(4, Bsz * Tt / 128), 256, GT_SMEM>>>(b_ih, b_hh);
    k_recur<<<Bsz / 2, 512, recur_smem>>>(Xe);
}

// round 17
// speedup vs baseline: 1.9010x; 1.9010x over previous
#include <cuda_runtime.h>
#include <cuda_bf16.h>
#include <math.h>
#include <stdint.h>

#define Bsz 256
#define Tt  128
#define Nn  512
#define Hh  128
#define G4  512   // 4*H

// Device scratch (no runtime alloc)
__device__ float g_Gpre[(size_t)Bsz * Tt * G4];          // 64 MB gate preacts
__device__ float g_whhT[Hh * G4];
__device__ __nv_bfloat16 g_Ahi[(size_t)Bsz * Tt * Nn];   // 32 MB
__device__ __nv_bfloat16 g_Alo[(size_t)Bsz * Tt * Nn];   // 32 MB
__device__ __nv_bfloat16 g_Whi[G4 * Nn];
__device__ __nv_bfloat16 g_Wlo[G4 * Nn];

// ======================= PTX helpers (generic-target only) ==================
__device__ __forceinline__ uint32_t smem_u32(const void* p) {
    uint32_t a;
    asm("{ .reg .u64 t; cvta.to.shared.u64 t, %1; cvt.u32.u64 %0, t; }"
        : "=r"(a) : "l"(p));
    return a;
}
__device__ __forceinline__ void cpa16(uint32_t dst, const void* src) {
    asm volatile("cp.async.cg.shared.global [%0], [%1], 16;"
                 :: "r"(dst), "l"(src) : "memory");
}
__device__ __forceinline__ void cpa_commit() {
    asm volatile("cp.async.commit_group;" ::: "memory");
}
__device__ __forceinline__ void cpa_wait0() {
    asm volatile("cp.async.wait_group 0;" ::: "memory");
}
__device__ __forceinline__ void ldsm4(uint32_t* r, uint32_t a) {
    asm volatile("ldmatrix.sync.aligned.m8n8.x4.shared.b16 {%0,%1,%2,%3}, [%4];"
                 : "=r"(r[0]), "=r"(r[1]), "=r"(r[2]), "=r"(r[3]) : "r"(a));
}
__device__ __forceinline__ void mma16816(float* d, const uint32_t* a,
                                         const uint32_t* b) {
    asm volatile("mma.sync.aligned.m16n8k16.row.col.f32.bf16.bf16.f32 "
        "{%0,%1,%2,%3}, {%4,%5,%6,%7}, {%8,%9}, {%0,%1,%2,%3};"
        : "+f"(d[0]), "+f"(d[1]), "+f"(d[2]), "+f"(d[3])
        : "r"(a[0]), "r"(a[1]), "r"(a[2]), "r"(a[3]), "r"(b[0]), "r"(b[1]));
}
// Packed fp32x2 FMA (exact fp32 pair; may scalarize on this toolchain)
__device__ __forceinline__ void fma2(unsigned long long& d,
                                     unsigned long long a, unsigned long long b) {
    asm("fma.rn.f32x2 %0, %1, %2, %0;" : "+l"(d) : "l"(a), "l"(b));
}
__device__ __forceinline__ unsigned long long dup2(float v) {
    unsigned long long r;
    asm("mov.b64 %0, {%1, %1};" : "=l"(r) : "f"(v));
    return r;
}
// Swizzled smem address for GEMM tiles: rows of 64B (4 x 16B granules).
__device__ __forceinline__ uint32_t sw_addr(uint32_t base, int r, int c) {
    uint32_t g = (uint32_t)(r * 4 + c);
    return base + ((g ^ ((g >> 2) & 7)) << 4);
}

// ---------------------------------------------------------------------------
// w_hh (4H, H) -> w_hhT (H, 4H)
// ---------------------------------------------------------------------------
__global__ void k_transpose_whh(const float* __restrict__ whh) {
    int idx = blockIdx.x * blockDim.x + threadIdx.x;
    if (idx < Hh * G4) {
        int k = idx >> 9;
        int j = idx & 511;
        g_whhT[idx] = whh[j * Hh + k];
    }
}

// ---------------------------------------------------------------------------
// w_ih -> hi/lo bf16 split
// ---------------------------------------------------------------------------
__global__ void k_convert_w(const float* __restrict__ wih) {
    int idx = blockIdx.x * blockDim.x + threadIdx.x;
    if (idx < G4 * Nn) {
        float v = wih[idx];
        __nv_bfloat16 hi = __float2bfloat16(v);
        g_Whi[idx] = hi;
        g_Wlo[idx] = __float2bfloat16(v - __bfloat162float(hi));
    }
}

// ---------------------------------------------------------------------------
// alpha = softmax_n(sum_t X*w_x); Xt = alpha .* X (time-invariant alpha).
// Also emits the hi/lo bf16 split of Xt for the tensor-core GEMM.
// ---------------------------------------------------------------------------
__global__ __launch_bounds__(512) void k_alpha(const float* __restrict__ X,
                                               const float* __restrict__ attn_w,
                                               float* __restrict__ Xt) {
    int b = blockIdx.x;
    int n = threadIdx.x;
    __shared__ float wx[Tt];
    __shared__ float redm[17];
    __shared__ float reds[17];
    if (n < Tt) wx[n] = attn_w[2 * Hh + n];
    __syncthreads();

    const float* Xb = X + (size_t)b * Tt * Nn;
    float acc = 0.f;
#pragma unroll 8
    for (int t = 0; t < Tt; t++)
        acc = fmaf(Xb[t * Nn + n], wx[t], acc);

    float v = acc;
#pragma unroll
    for (int o = 16; o > 0; o >>= 1)
        v = fmaxf(v, __shfl_xor_sync(0xffffffffu, v, o));
    if ((n & 31) == 0) redm[n >> 5] = v;
    __syncthreads();
    if (n < 32) {
        float m = (n < 16) ? redm[n] : -3.402823466e38f;
#pragma unroll
        for (int o = 16; o > 0; o >>= 1)
            m = fmaxf(m, __shfl_xor_sync(0xffffffffu, m, o));
        if (n == 0) redm[16] = m;
    }
    __syncthreads();
    float mx = redm[16];

    float e = __expf(acc - mx);
    v = e;
#pragma unroll
    for (int o = 16; o > 0; o >>= 1)
        v += __shfl_xor_sync(0xffffffffu, v, o);
    if ((n & 31) == 0) reds[n >> 5] = v;
    __syncthreads();
    if (n < 32) {
        float s = (n < 16) ? reds[n] : 0.f;
#pragma unroll
        for (int o = 16; o > 0; o >>= 1)
            s += __shfl_xor_sync(0xffffffffu, s, o);
        if (n == 0) reds[16] = s;
    }
    __syncthreads();
    float alpha = e / reds[16];

    float* Ot = Xt + (size_t)b * Tt * Nn;
    __nv_bfloat16* Ah = g_Ahi + (size_t)b * Tt * Nn;
    __nv_bfloat16* Al = g_Alo + (size_t)b * Tt * Nn;
#pragma unroll 4
    for (int t = 0; t < Tt; t++) {
        float xv = alpha * Xb[t * Nn + n];
        Ot[t * Nn + n] = xv;
        __nv_bfloat16 hi = __float2bfloat16(xv);
        Ah[t * Nn + n] = hi;
        Al[t * Nn + n] = __float2bfloat16(xv - __bfloat162float(hi));
    }
}

// ---------------------------------------------------------------------------
// bf16x3 warp-MMA GEMM (R13/R14 validated config: 2-stage double buffer,
// 64 KB smem -> 2 CTAs/SM; tensor=67.5%).
// ---------------------------------------------------------------------------
#define CHUNK_BYTES 32768        // 4 tiles x 8 KB (Ahi, Alo, Bhi, Blo)
#define GT_SMEM (2 * CHUNK_BYTES)

__device__ __forceinline__ void stage_chunk(uint32_t bbase, int kc, int tid,
                                            const __nv_bfloat16* PAh,
                                            const __nv_bfloat16* PAl,
                                            const __nv_bfloat16* PBh,
                                            const __nv_bfloat16* PBl) {
    const __nv_bfloat16* P[4] = { PAh, PAl, PBh, PBl };
#pragma unroll
    for (int t = 0; t < 4; t++) {
        uint32_t toff = bbase + t * 8192;
#pragma unroll
        for (int q = 0; q < 2; q++) {
            uint32_t G = (uint32_t)tid + q * 256;   // granule 0..511
            uint32_t r = G >> 2, c = G & 3;
            uint32_t swg = G ^ ((G >> 2) & 7);
            cpa16(toff + (swg << 4), P[t] + (size_t)r * 512 + kc * 32 + c * 8);
        }
    }
}

__global__ __launch_bounds__(256) void k_gemm_mma(const float* __restrict__ bih,
                                                  const float* __restrict__ bhh) {
    extern __shared__ char smp[];
    uint32_t sb = smem_u32(smp);
    int tid  = threadIdx.x;
    int lane = tid & 31;
    int wid  = tid >> 5;
    int bn   = blockIdx.x;   // 0..3
    int bm   = blockIdx.y;   // 0..255
    int m0w  = (wid & 1) * 64;
    int n0w  = (wid >> 1) * 32;

    const __nv_bfloat16* PAh = g_Ahi + (size_t)bm * 128 * 512;
    const __nv_bfloat16* PAl = g_Alo + (size_t)bm * 128 * 512;
    const __nv_bfloat16* PBh = g_Whi + (size_t)bn * 128 * 512;
    const __nv_bfloat16* PBl = g_Wlo + (size_t)bn * 128 * 512;

    float d[4][4][4];
#pragma unroll
    for (int i = 0; i < 4; i++)
#pragma unroll
        for (int j = 0; j < 4; j++)
#pragma unroll
            for (int q = 0; q < 4; q++) d[i][j][q] = 0.f;

    stage_chunk(sb, 0, tid, PAh, PAl, PBh, PBl);
    cpa_commit();

    int buf = 0;
    for (int kc = 0; kc < 16; kc++) {
        cpa_wait0();
        __syncthreads();
        if (kc + 1 < 16) {
            stage_chunk(sb + (buf ^ 1) * CHUNK_BYTES, kc + 1, tid,
                        PAh, PAl, PBh, PBl);
            cpa_commit();
        }
        uint32_t Ah = sb + buf * CHUNK_BYTES;
        uint32_t Al = Ah + 8192;
        uint32_t Bh = Ah + 16384;
        uint32_t Bl = Ah + 24576;

#pragma unroll
        for (int s = 0; s < 2; s++) {        // two K=16 steps per chunk
            uint32_t bh[4][2], bl[4][2];
#pragma unroll
            for (int jp = 0; jp < 2; jp++) { // each x4 covers 2 n-frags
                uint32_t tmp[4];
                int rowb = n0w + jp * 16 + (lane & 7) + ((lane >> 4) << 3);
                int cb   = s * 2 + ((lane >> 3) & 1);
                ldsm4(tmp, sw_addr(Bh, rowb, cb));
                bh[jp * 2][0] = tmp[0]; bh[jp * 2][1] = tmp[1];
                bh[jp * 2 + 1][0] = tmp[2]; bh[jp * 2 + 1][1] = tmp[3];
                ldsm4(tmp, sw_addr(Bl, rowb, cb));
                bl[jp * 2][0] = tmp[0]; bl[jp * 2][1] = tmp[1];
                bl[jp * 2 + 1][0] = tmp[2]; bl[jp * 2 + 1][1] = tmp[3];
            }
#pragma unroll
            for (int i = 0; i < 4; i++) {
                uint32_t ah[4], al[4];
                int rowa = m0w + i * 16 + (lane & 15);
                int ca   = s * 2 + (lane >> 4);
                ldsm4(ah, sw_addr(Ah, rowa, ca));
                ldsm4(al, sw_addr(Al, rowa, ca));
#pragma unroll
                for (int j = 0; j < 4; j++) {
                    mma16816(d[i][j], ah, bh[j]);
                    mma16816(d[i][j], ah, bl[j]);
                    mma16816(d[i][j], al, bh[j]);
                }
            }
        }
        buf ^= 1;
    }

    // Epilogue: bias add + fp32 store.
#pragma unroll
    for (int j = 0; j < 4; j++) {
        int col = bn * 128 + n0w + j * 8 + (lane & 3) * 2;
        float b0 = bih[col] + bhh[col];
        float b1 = bih[col + 1] + bhh[col + 1];
#pragma unroll
        for (int i = 0; i < 4; i++) {
            int row = bm * 128 + m0w + i * 16 + (lane >> 2);
            float2 v0 = make_float2(d[i][j][0] + b0, d[i][j][1] + b1);
            float2 v1 = make_float2(d[i][j][2] + b0, d[i][j][3] + b1);
            *(float2*)(g_Gpre + (size_t)row * 512 + col) = v0;
            *(float2*)(g_Gpre + (size_t)(row + 8) * 512 + col) = v1;
        }
    }
}

// ---------------------------------------------------------------------------
// LSTM recurrence v3 (R14 validated, ~215us) + fast exp-based activations.
// 128 blocks x 2 batches, 512 threads.
//   thread (kk = tid>>7, jg = tid&127): gate quad j4 = jg*4, both batches,
//   k-slice [kk*32, kk*32+32); rows [kb,kb+16) in registers, rest in smem.
// ---------------------------------------------------------------------------
#define RSM_W (4 * 16 * G4)   // 32768 floats of smem weights (128 KB)

__device__ __forceinline__ float sigm(float x) {
    return __fdividef(1.f, 1.f + __expf(-x));
}
__device__ __forceinline__ float tanh_e(float x) {
    return 1.f - __fdividef(2.f, __expf(2.f * x) + 1.f);
}

__global__ __launch_bounds__(512, 1) void k_recur(float* __restrict__ Xe) {
    extern __shared__ float sm[];
    float* ws = sm;                                   // [4][16][512]
    float* pg = ws + RSM_W;                           // [8][512] partials
    float* cs = pg + 8 * G4;                          // [2][128]
    unsigned long long* hs2 =
        (unsigned long long*)(cs + 2 * Hh);           // [2][128] {h,h} packed

    int tid = threadIdx.x;
    int b0  = blockIdx.x * 2;
    int kk    = tid >> 7;
    int jg    = tid & 127;
    int j4    = jg * 4;
    int kbase = kk * 32;

    // stage smem weight half: ws row r (0..63) <- g_whhT row kk*32+16+(r&15)
    for (int i = tid; i < RSM_W / 4; i += 512) {
        int r = i >> 7;          // 128 float4 granules per row
        int c = i & 127;
        int grow = (r >> 4) * 32 + 16 + (r & 15);
        ((float4*)ws)[i] = *(const float4*)(g_whhT + (size_t)grow * 512 + c * 4);
    }
    if (tid < 256) {
        cs[tid] = 0.f;
        hs2[tid] = 0ull;
    }

    // register weight half: k in [kbase, kbase+16)
    ulonglong2 wreg[16];
#pragma unroll
    for (int kr = 0; kr < 16; kr++)
        wreg[kr] = *(const ulonglong2*)(g_whhT + (size_t)(kbase + kr) * 512 + j4);
    __syncthreads();

    int ubi  = tid >> 7;          // valid when tid<256
    int uhid = tid & 127;
    const float* Gu = g_Gpre + (size_t)(b0 + ubi) * Tt * G4 + uhid;

    const unsigned long long* h0 = hs2;
    const unsigned long long* h1 = hs2 + Hh;
    const float* wsm_t = ws + (size_t)(kk * 16) * G4 + j4;

    for (int t = 0; t < Tt; t++) {
        // prefetch gate preactivations (resolve under the matvec)
        float pi = 0.f, pf = 0.f, pgt = 0.f, po = 0.f;
        if (tid < 256) {
            const float* gp = Gu + (size_t)t * G4;
            pi  = __ldg(gp);
            pf  = __ldg(gp + Hh);
            pgt = __ldg(gp + 2 * Hh);
            po  = __ldg(gp + 3 * Hh);
        }

        ulonglong2 a0, a1;
        a0.x = 0ull; a0.y = 0ull; a1.x = 0ull; a1.y = 0ull;

        // ---- register-weight half ----
#pragma unroll
        for (int kr = 0; kr < 16; kr += 2) {
            ulonglong2 hh0 = *(const ulonglong2*)(h0 + kbase + kr);
            ulonglong2 hh1 = *(const ulonglong2*)(h1 + kbase + kr);
            fma2(a0.x, wreg[kr].x, hh0.x);     fma2(a0.y, wreg[kr].y, hh0.x);
            fma2(a1.x, wreg[kr].x, hh1.x);     fma2(a1.y, wreg[kr].y, hh1.x);
            fma2(a0.x, wreg[kr + 1].x, hh0.y); fma2(a0.y, wreg[kr + 1].y, hh0.y);
            fma2(a1.x, wreg[kr + 1].x, hh1.y); fma2(a1.y, wreg[kr + 1].y, hh1.y);
        }
        // ---- smem-weight half ----
#pragma unroll
        for (int kr = 0; kr < 16; kr += 2) {
            ulonglong2 hh0 = *(const ulonglong2*)(h0 + kbase + 16 + kr);
            ulonglong2 hh1 = *(const ulonglong2*)(h1 + kbase + 16 + kr);
            ulonglong2 w0 = *(const ulonglong2*)(wsm_t + (size_t)(kr + 0) * G4);
            ulonglong2 w1 = *(const ulonglong2*)(wsm_t + (size_t)(kr + 1) * G4);
            fma2(a0.x, w0.x, hh0.x); fma2(a0.y, w0.y, hh0.x);
            fma2(a1.x, w0.x, hh1.x); fma2(a1.y, w0.y, hh1.x);
            fma2(a0.x, w1.x, hh0.y); fma2(a0.y, w1.y, hh0.y);
            fma2(a1.x, w1.x, hh1.y); fma2(a1.y, w1.y, hh1.y);
        }
        *(ulonglong2*)(pg + (kk * 2 + 0) * G4 + j4) = a0;
        *(ulonglong2*)(pg + (kk * 2 + 1) * G4 + j4) = a1;
        __syncthreads();

        // ---- reduce partials + LSTM cell update (256 threads) ----
        if (tid < 256) {
            float gi = pi, gf = pf, gg = pgt, go = po;
#pragma unroll
            for (int q = 0; q < 4; q++) {
                const float* pr = pg + (q * 2 + ubi) * G4 + uhid;
                gi += pr[0];
                gf += pr[Hh];
                gg += pr[2 * Hh];
                go += pr[3 * Hh];
            }
            float cn = sigm(gf) * cs[ubi * Hh + uhid] + sigm(gi) * tanh_e(gg);
            float hn = sigm(go) * tanh_e(cn);
            cs[ubi * Hh + uhid] = cn;
            hs2[ubi * Hh + uhid] = dup2(hn);
            Xe[((size_t)(b0 + ubi) * Tt + t) * Hh + uhid] = hn;
        }
        __syncthreads();
    }
}

// ---------------------------------------------------------------------------
extern "C" void kernel_launch(void* const* d_in, const int* in_sizes, int n_in,
                              void* d_out, int out_size) {
    const float* X      = (const float*)d_in[0];
    const float* attn_w = (const float*)d_in[1];
    // d_in[2] = attn_b: dead (softmax shift-invariance), as are attn_w[0:2H]
    const float* w_ih   = (const float*)d_in[3];
    const float* w_hh   = (const float*)d_in[4];
    const float* b_ih   = (const float*)d_in[5];
    const float* b_hh   = (const float*)d_in[6];

    float* out = (float*)d_out;
    float* Xt  = out;                                  // (B,T,N)
    float* Xe  = out + (size_t)Bsz * Tt * Nn;          // (B,T,H)

    const int recur_smem =
        (RSM_W + 8 * G4 + 2 * Hh) * (int)sizeof(float) + 2 * Hh * 8;  // 150528 B
    cudaFuncSetAttribute(k_recur, cudaFuncAttributeMaxDynamicSharedMemorySize,
                         recur_smem);
    cudaFuncSetAttribute(k_gemm_mma, cudaFuncAttributeMaxDynamicSharedMemorySize,
                         GT_SMEM);

    k_transpose_whh<<<(Hh * G4 + 255) / 256, 256>>>(w_hh);
    k_convert_w<<<(G4 * Nn + 255) / 256, 256>>>(w_ih);
    k_alpha<<<Bsz, 512>>>(X, attn_w, Xt);
    k_gemm_mma<<<dim3(4, Bsz * Tt / 128), 256, GT_SMEM>>>(b_ih, b_hh);
    k_recur<<<Bsz / 2, 512, recur_smem>>>(Xe);
}